// round 16
// baseline (speedup 1.0000x reference)
#include <cuda_runtime.h>
#include <cuda_fp16.h>
#include <math.h>
#include <cstdint>

#define N_NODES 100000
#define E_EDGES 1600000
#define HD 128
#define OD 40
#define NLAYERS 4
#define SCALE 0.08838834764831845f  // 1/sqrt(128)

#define SCAN_BLK 1024
#define NSCANB ((N_NODES + SCAN_BLK - 1) / SCAN_BLK)   // 98

// ---------------- device scratch (no allocations allowed) ----------------
__device__ float  g_h[(size_t)N_NODES * HD];
__device__ float  g_q[(size_t)N_NODES * HD];      // qm = h @ M
__device__ float  g_s[(size_t)N_NODES * HD];      // skip GEMM output
__device__ float  g_agg[(size_t)N_NODES * HD];    // softmax-weighted h aggregate
__device__ __half g_kv[(size_t)N_NODES * HD];     // h16 (gather source)
__device__ float  g_beta[N_NODES];
__device__ float  g_M[NLAYERS * HD * HD];         // SCALE * Wq @ Wk^T, per layer
__device__ float  g_w[NLAYERS * HD];              // SCALE * Wk @ bq, per layer
__device__ float  g_zero[HD];                     // stays zero (bias for qm GEMM)
__device__ int    g_deg[N_NODES];
__device__ int    g_rowstart[N_NODES + 1];
__device__ int    g_cursor[N_NODES];
__device__ int    g_bsum[NSCANB];
__device__ int    g_esrc[E_EDGES];

// ==================== bilinear prep for ALL layers (weights-only) ====================
#define PREP_SMEM ((128 * 132 + 8 * 132 + 128) * 4)

__global__ __launch_bounds__(256)
void prep_all(const float* __restrict__ Wq, const float* __restrict__ Wk,
              const float* __restrict__ bq)
{
    extern __shared__ float ps[];
    float* Wqs = ps;                    // [c*132 + a]
    float* Wks = ps + 128 * 132;        // [b_local*132 + c]
    float* bqs = Wks + 8 * 132;

    const int tid   = threadIdx.x;
    const int layer = blockIdx.x >> 4;
    const int b0    = (blockIdx.x & 15) * 8;
    const float* Wq_l = Wq + (size_t)layer * HD * HD;
    const float* Wk_l = Wk + (size_t)layer * HD * HD;
    const float* bq_l = bq + (size_t)layer * HD;

    for (int idx = tid; idx < 128 * 32; idx += 256) {
        int a  = idx >> 5;
        int c4 = (idx & 31) * 4;
        float4 w4 = *reinterpret_cast<const float4*>(&Wq_l[a * 128 + c4]);
        Wqs[(c4 + 0) * 132 + a] = w4.x;
        Wqs[(c4 + 1) * 132 + a] = w4.y;
        Wqs[(c4 + 2) * 132 + a] = w4.z;
        Wqs[(c4 + 3) * 132 + a] = w4.w;
    }
    for (int i = tid; i < 8 * 32; i += 256) {
        int b  = i >> 5;
        int c4 = (i & 31) * 4;
        *reinterpret_cast<float4*>(&Wks[b * 132 + c4]) =
            *reinterpret_cast<const float4*>(&Wk_l[(b0 + b) * 128 + c4]);
    }
    if (tid < 128) bqs[tid] = bq_l[tid];
    __syncthreads();

    const int a  = tid & 127;
    const int bh = tid >> 7;
    float acc[4] = {0.f, 0.f, 0.f, 0.f};
    #pragma unroll 4
    for (int c = 0; c < 128; c++) {
        float wq = Wqs[c * 132 + a];
        #pragma unroll
        for (int j = 0; j < 4; j++)
            acc[j] += wq * Wks[(bh * 4 + j) * 132 + c];
    }
    #pragma unroll
    for (int j = 0; j < 4; j++)
        g_M[(size_t)layer * HD * HD + a * 128 + b0 + bh * 4 + j] = acc[j] * SCALE;

    if (tid < 8) {
        float s = 0.f;
        for (int c = 0; c < 128; c++) s += Wks[tid * 132 + c] * bqs[c];
        g_w[layer * HD + b0 + tid] = s * SCALE;
    }
}

// ==================== shared GEMM tile machinery (FFMA, at the issue roofline) ====================
#define GPITCH 132
#define GEMM_SMEM (2 * 128 * GPITCH * 4)

// ==================== per-layer GEMM: y=0 qm(+beta), y=1 s ====================
__global__ __launch_bounds__(256, 1)
void gemm2(const float* __restrict__ A,
           const float* __restrict__ W0, const float* __restrict__ W1,
           const float* __restrict__ b1,
           float* __restrict__ qm, float* __restrict__ sout,
           const float* __restrict__ wvec, float* __restrict__ betap,
           int nrows)
{
    extern __shared__ float sm[];
    float* AsT = sm;                   // [k*GPITCH + m]
    float* Ws  = sm + 128 * GPITCH;    // [k*GPITCH + n]
    __shared__ float wsh[128];

    const int y = blockIdx.y;
    const float* W = (y == 0) ? W0 : W1;

    const int tid  = threadIdx.x;
    const int row0 = blockIdx.x * 128;

    #pragma unroll
    for (int c = 0; c < 16; c++) {
        int idx = c * 256 + tid;
        int r   = idx & 127;
        int kq  = (idx >> 7) * 4;
        int ar  = row0 + r;
        float4 a4 = make_float4(0.f, 0.f, 0.f, 0.f);
        if (ar < nrows) a4 = *reinterpret_cast<const float4*>(&A[(size_t)ar * 128 + kq]);
        AsT[(kq + 0) * GPITCH + r] = a4.x;
        AsT[(kq + 1) * GPITCH + r] = a4.y;
        AsT[(kq + 2) * GPITCH + r] = a4.z;
        AsT[(kq + 3) * GPITCH + r] = a4.w;
    }
    #pragma unroll
    for (int c = 0; c < 16; c++) {
        int idx = c * 256 + tid;
        int r   = idx >> 5;
        int c4  = (idx & 31) * 4;
        *reinterpret_cast<float4*>(&Ws[r * GPITCH + c4]) =
            *reinterpret_cast<const float4*>(&W[r * 128 + c4]);
    }
    if (tid < 128) wsh[tid] = wvec[tid];
    __syncthreads();

    const int tx = tid & 15, ty = tid >> 4;
    const int r0 = ty * 8, c0 = tx * 8;

    float acc[8][8];
    #pragma unroll
    for (int i = 0; i < 8; i++)
        #pragma unroll
        for (int j = 0; j < 8; j++) acc[i][j] = 0.f;

    #pragma unroll 8
    for (int k = 0; k < 128; k++) {
        float4 a0 = *reinterpret_cast<const float4*>(&AsT[k * GPITCH + r0]);
        float4 a1 = *reinterpret_cast<const float4*>(&AsT[k * GPITCH + r0 + 4]);
        float a[8] = {a0.x, a0.y, a0.z, a0.w, a1.x, a1.y, a1.z, a1.w};
        float4 bb0 = *reinterpret_cast<const float4*>(&Ws[k * GPITCH + c0]);
        float4 bb1 = *reinterpret_cast<const float4*>(&Ws[k * GPITCH + c0 + 4]);
        float b[8] = {bb0.x, bb0.y, bb0.z, bb0.w, bb1.x, bb1.y, bb1.z, bb1.w};
        #pragma unroll
        for (int i = 0; i < 8; i++)
            #pragma unroll
            for (int j = 0; j < 8; j++) acc[i][j] += a[i] * b[j];
    }

    if (y == 0 && tid < 128) {
        int rr = row0 + tid;
        if (rr < nrows) {
            float bsum = 0.f;
            #pragma unroll 8
            for (int b = 0; b < 128; b++) bsum += AsT[b * GPITCH + tid] * wsh[b];
            betap[rr] = bsum;
        }
    }

    float bb[8];
    #pragma unroll
    for (int j = 0; j < 8; j++) bb[j] = (y == 0) ? 0.f : b1[c0 + j];

    float* outf = (y == 0) ? qm : sout;
    #pragma unroll
    for (int i = 0; i < 8; i++) {
        int r = row0 + r0 + i;
        if (r >= nrows) continue;
        float4 o0 = make_float4(acc[i][0] + bb[0], acc[i][1] + bb[1],
                                acc[i][2] + bb[2], acc[i][3] + bb[3]);
        float4 o1 = make_float4(acc[i][4] + bb[4], acc[i][5] + bb[5],
                                acc[i][6] + bb[6], acc[i][7] + bb[7]);
        *reinterpret_cast<float4*>(&outf[(size_t)r * 128 + c0])     = o0;
        *reinterpret_cast<float4*>(&outf[(size_t)r * 128 + c0 + 4]) = o1;
    }
}

// ==================== fused post-GEMM: out = [elu](A@W + cond_bias + skip) ====================
// Serves the input projection (skip=null, deg=null, elu=0) and the per-layer
// Wv step (A=agg; bias bv added only where deg>0 — matches reference's agg=0
// for isolated nodes). Always writes fp32 out + fp16 dual into kv.
__global__ __launch_bounds__(256, 1)
void gemm_post(const float* __restrict__ A, const float* __restrict__ W,
               const float* __restrict__ bias, const float* __restrict__ skip,
               const int* __restrict__ deg,
               float* __restrict__ outf, __half* __restrict__ kvh,
               int apply_elu, int nrows)
{
    extern __shared__ float sm[];
    float* AsT = sm;
    float* Ws  = sm + 128 * GPITCH;

    const int tid  = threadIdx.x;
    const int row0 = blockIdx.x * 128;

    #pragma unroll
    for (int c = 0; c < 16; c++) {
        int idx = c * 256 + tid;
        int r   = idx & 127;
        int kq  = (idx >> 7) * 4;
        int ar  = row0 + r;
        float4 a4 = make_float4(0.f, 0.f, 0.f, 0.f);
        if (ar < nrows) a4 = *reinterpret_cast<const float4*>(&A[(size_t)ar * 128 + kq]);
        AsT[(kq + 0) * GPITCH + r] = a4.x;
        AsT[(kq + 1) * GPITCH + r] = a4.y;
        AsT[(kq + 2) * GPITCH + r] = a4.z;
        AsT[(kq + 3) * GPITCH + r] = a4.w;
    }
    #pragma unroll
    for (int c = 0; c < 16; c++) {
        int idx = c * 256 + tid;
        int r   = idx >> 5;
        int c4  = (idx & 31) * 4;
        *reinterpret_cast<float4*>(&Ws[r * GPITCH + c4]) =
            *reinterpret_cast<const float4*>(&W[r * 128 + c4]);
    }
    __syncthreads();

    const int tx = tid & 15, ty = tid >> 4;
    const int r0 = ty * 8, c0 = tx * 8;

    float acc[8][8];
    #pragma unroll
    for (int i = 0; i < 8; i++)
        #pragma unroll
        for (int j = 0; j < 8; j++) acc[i][j] = 0.f;

    #pragma unroll 8
    for (int k = 0; k < 128; k++) {
        float4 a0 = *reinterpret_cast<const float4*>(&AsT[k * GPITCH + r0]);
        float4 a1 = *reinterpret_cast<const float4*>(&AsT[k * GPITCH + r0 + 4]);
        float a[8] = {a0.x, a0.y, a0.z, a0.w, a1.x, a1.y, a1.z, a1.w};
        float4 bb0 = *reinterpret_cast<const float4*>(&Ws[k * GPITCH + c0]);
        float4 bb1 = *reinterpret_cast<const float4*>(&Ws[k * GPITCH + c0 + 4]);
        float b[8] = {bb0.x, bb0.y, bb0.z, bb0.w, bb1.x, bb1.y, bb1.z, bb1.w};
        #pragma unroll
        for (int i = 0; i < 8; i++)
            #pragma unroll
            for (int j = 0; j < 8; j++) acc[i][j] += a[i] * b[j];
    }

    float bb[8];
    #pragma unroll
    for (int j = 0; j < 8; j++) bb[j] = bias[c0 + j];

    #pragma unroll
    for (int i = 0; i < 8; i++) {
        int r = row0 + r0 + i;
        if (r >= nrows) continue;
        float bscale = (deg == nullptr || deg[r] > 0) ? 1.f : 0.f;
        float o[8];
        #pragma unroll
        for (int j = 0; j < 8; j++) o[j] = acc[i][j] + bscale * bb[j];
        if (skip) {
            float4 s0 = *reinterpret_cast<const float4*>(&skip[(size_t)r * 128 + c0]);
            float4 s1 = *reinterpret_cast<const float4*>(&skip[(size_t)r * 128 + c0 + 4]);
            o[0] += s0.x; o[1] += s0.y; o[2] += s0.z; o[3] += s0.w;
            o[4] += s1.x; o[5] += s1.y; o[6] += s1.z; o[7] += s1.w;
        }
        if (apply_elu) {
            #pragma unroll
            for (int j = 0; j < 8; j++) o[j] = o[j] > 0.f ? o[j] : expm1f(o[j]);
        }
        float4 o0 = make_float4(o[0], o[1], o[2], o[3]);
        float4 o1 = make_float4(o[4], o[5], o[6], o[7]);
        *reinterpret_cast<float4*>(&outf[(size_t)r * 128 + c0])     = o0;
        *reinterpret_cast<float4*>(&outf[(size_t)r * 128 + c0 + 4]) = o1;
        __half2 h4[4];
        #pragma unroll
        for (int j = 0; j < 4; j++)
            h4[j] = __floats2half2_rn(o[2 * j], o[2 * j + 1]);
        *reinterpret_cast<uint4*>(&kvh[(size_t)r * 128 + c0]) =
            *reinterpret_cast<uint4*>(h4);
    }
}

// ==================== CSR build (once per launch) ====================
__global__ void csr_zero(int* __restrict__ deg) {
    int n = blockIdx.x * blockDim.x + threadIdx.x;
    if (n < N_NODES) deg[n] = 0;
}

__global__ __launch_bounds__(256)
void csr_count(const int* __restrict__ ei, int* __restrict__ deg) {
    int e = blockIdx.x * blockDim.x + threadIdx.x;
    if (e >= E_EDGES) return;
    atomicAdd(&deg[ei[E_EDGES + e]], 1);
}

__global__ __launch_bounds__(SCAN_BLK)
void csr_scan1(const int* __restrict__ deg, int* __restrict__ rowstart,
               int* __restrict__ bsum)
{
    __shared__ int wsum[32];
    const int tid  = threadIdx.x;
    const int lane = tid & 31;
    const int wid  = tid >> 5;
    const int n    = blockIdx.x * SCAN_BLK + tid;

    int v = (n < N_NODES) ? deg[n] : 0;
    int x = v;
    #pragma unroll
    for (int o = 1; o < 32; o <<= 1) {
        int yv = __shfl_up_sync(0xFFFFFFFFu, x, o);
        if (lane >= o) x += yv;
    }
    if (lane == 31) wsum[wid] = x;
    __syncthreads();
    if (wid == 0) {
        int w = wsum[lane];
        #pragma unroll
        for (int o = 1; o < 32; o <<= 1) {
            int yv = __shfl_up_sync(0xFFFFFFFFu, w, o);
            if (lane >= o) w += yv;
        }
        wsum[lane] = w;
    }
    __syncthreads();
    int excl = x - v + (wid ? wsum[wid - 1] : 0);
    if (n < N_NODES) rowstart[n] = excl;
    if (tid == SCAN_BLK - 1) bsum[blockIdx.x] = excl + v;
}

__global__ __launch_bounds__(128)
void csr_scan2(int* __restrict__ bsum)
{
    __shared__ int sh[NSCANB];
    const int tid = threadIdx.x;
    if (tid < NSCANB) sh[tid] = bsum[tid];
    __syncthreads();
    if (tid == 0) {
        int run = 0;
        for (int i = 0; i < NSCANB; i++) { int t = sh[i]; sh[i] = run; run += t; }
    }
    __syncthreads();
    if (tid < NSCANB) bsum[tid] = sh[tid];
}

__global__ __launch_bounds__(SCAN_BLK)
void csr_scan3(int* __restrict__ rowstart, int* __restrict__ cursor,
               const int* __restrict__ bsum)
{
    const int n = blockIdx.x * SCAN_BLK + threadIdx.x;
    if (n < N_NODES) {
        int r = rowstart[n] + bsum[blockIdx.x];
        rowstart[n] = r;
        cursor[n]   = r;
    }
    if (n == 0) rowstart[N_NODES] = E_EDGES;
}

__global__ __launch_bounds__(256)
void csr_scatter(const int* __restrict__ ei, int* __restrict__ cursor,
                 int* __restrict__ esrc)
{
    int e = blockIdx.x * blockDim.x + threadIdx.x;
    if (e >= E_EDGES) return;
    int dst  = ei[E_EDGES + e];
    int slot = atomicAdd(&cursor[dst], 1);
    esrc[slot] = ei[e];
}

// ==================== per-node attention aggregation over h16 ====================
// logit_e = qm[dst].h16[src] + beta[src]; agg_n = (Σ e·h16[src]) / Σ e.
// Only h16 is gathered (256B/edge) — the same row feeds logit AND aggregate.
__global__ __launch_bounds__(256)
void gat_node(const int* __restrict__ rowstart, const int* __restrict__ esrc,
              const float* __restrict__ qm, const __half* __restrict__ kh,
              const float* __restrict__ beta, float* __restrict__ agg)
{
    const int wid  = threadIdx.x >> 5;
    const int lane = threadIdx.x & 31;
    const int n    = blockIdx.x * 8 + wid;
    if (n >= N_NODES) return;

    const int beg = rowstart[n];
    const int end = rowstart[n + 1];

    float4 q4 = *reinterpret_cast<const float4*>(&qm[(size_t)n * 128 + lane * 4]);
    float4 acc = make_float4(0.f, 0.f, 0.f, 0.f);
    float  den = 0.f;

    if (beg < end) {
        int src = __ldg(&esrc[beg]);
        uint2 ku = __ldg(reinterpret_cast<const uint2*>(&kh[(size_t)src * 128 + lane * 4]));
        float bt = __ldg(&beta[src]);
        for (int i = beg; i < end; i++) {
            uint2 kc = ku;
            float bc = bt;
            if (i + 1 < end) {
                int s2 = __ldg(&esrc[i + 1]);
                ku = __ldg(reinterpret_cast<const uint2*>(&kh[(size_t)s2 * 128 + lane * 4]));
                bt = __ldg(&beta[s2]);
            }
            float2 k0 = __half22float2(*reinterpret_cast<__half2*>(&kc.x));
            float2 k1 = __half22float2(*reinterpret_cast<__half2*>(&kc.y));
            float p = q4.x * k0.x + q4.y * k0.y + q4.z * k1.x + q4.w * k1.y;
            #pragma unroll
            for (int off = 16; off > 0; off >>= 1)
                p += __shfl_xor_sync(0xFFFFFFFFu, p, off);
            float e = __expf(p + bc);
            den   += e;
            acc.x += e * k0.x; acc.y += e * k0.y;
            acc.z += e * k1.x; acc.w += e * k1.y;
        }
    }

    float inv = (beg < end) ? (1.f / den) : 0.f;
    float4 r = make_float4(acc.x * inv, acc.y * inv, acc.z * inv, acc.w * inv);
    *reinterpret_cast<float4*>(&agg[(size_t)n * 128 + lane * 4]) = r;
}

// ---------------- classifier: out = log_softmax(h @ fcW + fcb) ----------------
__global__ __launch_bounds__(256)
void classifier(const float* __restrict__ h, const float* __restrict__ fcW,
                const float* __restrict__ fcb, float* __restrict__ out)
{
    __shared__ float Wsh[128 * 64];
    __shared__ float hs[8][128];

    int tid = threadIdx.x;
    for (int i = tid; i < 128 * 64; i += 256) {
        int r = i >> 6, c = i & 63;
        Wsh[i] = (c < OD) ? fcW[r * OD + c] : 0.f;
    }
    __syncthreads();

    int wid  = tid >> 5;
    int lane = tid & 31;
    int n    = blockIdx.x * 8 + wid;
    if (n >= N_NODES) return;

    reinterpret_cast<float4*>(hs[wid])[lane] =
        reinterpret_cast<const float4*>(&h[(size_t)n * 128])[lane];
    __syncwarp();

    float acc0 = 0.f, acc1 = 0.f;
    #pragma unroll 8
    for (int k = 0; k < 128; k++) {
        float hv = hs[wid][k];
        acc0 += hv * Wsh[k * 64 + lane];
        acc1 += hv * Wsh[k * 64 + 32 + lane];
    }
    float val0 = acc0 + fcb[lane];
    float val1 = (lane < 8) ? (acc1 + fcb[32 + lane]) : -__int_as_float(0x7F800000);

    float vmax = fmaxf(val0, val1);
    #pragma unroll
    for (int off = 16; off > 0; off >>= 1)
        vmax = fmaxf(vmax, __shfl_xor_sync(0xFFFFFFFFu, vmax, off));

    float s = __expf(val0 - vmax) + ((lane < 8) ? __expf(val1 - vmax) : 0.f);
    #pragma unroll
    for (int off = 16; off > 0; off >>= 1)
        s += __shfl_xor_sync(0xFFFFFFFFu, s, off);

    float lse = vmax + logf(s);
    out[(size_t)n * OD + lane] = val0 - lse;
    if (lane < 8) out[(size_t)n * OD + 32 + lane] = val1 - lse;
}

// ---------------- host launch ----------------
extern "C" void kernel_launch(void* const* d_in, const int* in_sizes, int n_in,
                              void* d_out, int out_size)
{
    const float* x     = (const float*)d_in[0];
    const int*   ei    = (const int*)  d_in[1];
    const float* lin_W = (const float*)d_in[2];
    const float* lin_b = (const float*)d_in[3];
    const float* Wq    = (const float*)d_in[4];
    const float* bq    = (const float*)d_in[5];
    const float* Wk    = (const float*)d_in[6];
    const float* bk    = (const float*)d_in[7];   // cancels in softmax; unused
    const float* Wv    = (const float*)d_in[8];
    const float* bv    = (const float*)d_in[9];
    const float* Wsk   = (const float*)d_in[10];
    const float* bsk   = (const float*)d_in[11];
    const float* fcW   = (const float*)d_in[12];
    const float* fcb   = (const float*)d_in[13];
    float* out = (float*)d_out;
    (void)bk;

    float *h, *qm, *s, *agg, *beta, *Mp, *wp, *zerop;
    __half *kv;
    int *deg, *rowstart, *cursor, *esrc, *bsum;
    cudaGetSymbolAddress((void**)&h,        g_h);
    cudaGetSymbolAddress((void**)&qm,       g_q);
    cudaGetSymbolAddress((void**)&s,        g_s);
    cudaGetSymbolAddress((void**)&agg,      g_agg);
    cudaGetSymbolAddress((void**)&beta,     g_beta);
    cudaGetSymbolAddress((void**)&Mp,       g_M);
    cudaGetSymbolAddress((void**)&wp,       g_w);
    cudaGetSymbolAddress((void**)&zerop,    g_zero);
    cudaGetSymbolAddress((void**)&kv,       g_kv);
    cudaGetSymbolAddress((void**)&deg,      g_deg);
    cudaGetSymbolAddress((void**)&rowstart, g_rowstart);
    cudaGetSymbolAddress((void**)&cursor,   g_cursor);
    cudaGetSymbolAddress((void**)&esrc,     g_esrc);
    cudaGetSymbolAddress((void**)&bsum,     g_bsum);

    cudaFuncSetAttribute(gemm2,     cudaFuncAttributeMaxDynamicSharedMemorySize, GEMM_SMEM);
    cudaFuncSetAttribute(gemm_post, cudaFuncAttributeMaxDynamicSharedMemorySize, GEMM_SMEM);
    cudaFuncSetAttribute(prep_all,  cudaFuncAttributeMaxDynamicSharedMemorySize, PREP_SMEM);

    const int GB  = (N_NODES + 127) / 128;
    const int NB  = (N_NODES + 255) / 256;
    const int ETB = (E_EDGES + 255) / 256;
    const int WNB = (N_NODES + 7) / 8;

    // ---- weights-only prep for all layers (one launch) ----
    prep_all<<<64, 256, PREP_SMEM>>>(Wq, Wk, bq);

    // ---- CSR build (monotonic parallel scan; deterministic layout) ----
    csr_zero<<<NB, 256>>>(deg);
    csr_count<<<ETB, 256>>>(ei, deg);
    csr_scan1<<<NSCANB, SCAN_BLK>>>(deg, rowstart, bsum);
    csr_scan2<<<1, 128>>>(bsum);
    csr_scan3<<<NSCANB, SCAN_BLK>>>(rowstart, cursor, bsum);
    csr_scatter<<<ETB, 256>>>(ei, cursor, esrc);

    // ---- input projection: h = x@lin_W + lin_b (fp32 + dual h16 into kv) ----
    gemm_post<<<GB, 256, GEMM_SMEM>>>(
        x, lin_W, lin_b, nullptr, nullptr, h, kv, 0, N_NODES);

    for (int l = 0; l < NLAYERS; l++) {
        const float* Wv_l = Wv  + (size_t)l * HD * HD;
        const float* Ws_l = Wsk + (size_t)l * HD * HD;
        const float* bv_l = bv  + (size_t)l * HD;
        const float* bs_l = bsk + (size_t)l * HD;

        // qm = h@M_l (+beta), s = h@Ws_l
        gemm2<<<dim3(GB, 2), 256, GEMM_SMEM>>>(
            h, Mp + (size_t)l * HD * HD, Ws_l, bs_l,
            qm, s, wp + (size_t)l * HD, beta, N_NODES);

        // segment softmax + h16 aggregation (256B/edge gather)
        gat_node<<<WNB, 256>>>(rowstart, esrc, qm, kv, beta, agg);

        // h = [elu](agg@Wv + bv·[deg>0] + s); dual h16 into kv
        gemm_post<<<GB, 256, GEMM_SMEM>>>(
            agg, Wv_l, bv_l, s, deg, h, kv, (l < NLAYERS - 1) ? 1 : 0, N_NODES);
    }

    classifier<<<WNB, 256>>>(h, fcW, fcb, out);
}

// round 17
// speedup vs baseline: 1.1062x; 1.1062x over previous
#include <cuda_runtime.h>
#include <cuda_fp16.h>
#include <math.h>
#include <cstdint>

#define N_NODES 100000
#define E_EDGES 1600000
#define HD 128
#define OD 40
#define NLAYERS 4
#define SCALE 0.08838834764831845f  // 1/sqrt(128)

#define SCAN_BLK 1024
#define NSCANB ((N_NODES + SCAN_BLK - 1) / SCAN_BLK)   // 98

// ---------------- device scratch (no allocations allowed) ----------------
__device__ float  g_h[(size_t)N_NODES * HD];
__device__ float  g_q[(size_t)N_NODES * HD];      // qm = h @ M
__device__ float  g_s[(size_t)N_NODES * HD];      // skip GEMM output
__device__ __half g_kv0[(size_t)N_NODES * 256];   // [n][0:128]=h16, [n][128:256]=v16
__device__ __half g_kv1[(size_t)N_NODES * 256];
__device__ float  g_beta[N_NODES];
__device__ float  g_M[NLAYERS * HD * HD];         // SCALE * Wq @ Wk^T, per layer
__device__ float  g_w[NLAYERS * HD];              // SCALE * Wk @ bq, per layer
__device__ float  g_zero[HD];                     // stays zero (bias for qm GEMM)
__device__ int    g_deg[N_NODES];
__device__ int    g_rowstart[N_NODES + 1];
__device__ int    g_cursor[N_NODES];
__device__ int    g_bsum[NSCANB];
__device__ int    g_esrc[E_EDGES];

// ==================== bilinear prep for ALL layers (weights-only) ====================
#define PREP_SMEM ((128 * 132 + 8 * 132 + 128) * 4)

__global__ __launch_bounds__(256)
void prep_all(const float* __restrict__ Wq, const float* __restrict__ Wk,
              const float* __restrict__ bq)
{
    extern __shared__ float ps[];
    float* Wqs = ps;                    // [c*132 + a]
    float* Wks = ps + 128 * 132;        // [b_local*132 + c]
    float* bqs = Wks + 8 * 132;

    const int tid   = threadIdx.x;
    const int layer = blockIdx.x >> 4;
    const int b0    = (blockIdx.x & 15) * 8;
    const float* Wq_l = Wq + (size_t)layer * HD * HD;
    const float* Wk_l = Wk + (size_t)layer * HD * HD;
    const float* bq_l = bq + (size_t)layer * HD;

    for (int idx = tid; idx < 128 * 32; idx += 256) {
        int a  = idx >> 5;
        int c4 = (idx & 31) * 4;
        float4 w4 = *reinterpret_cast<const float4*>(&Wq_l[a * 128 + c4]);
        Wqs[(c4 + 0) * 132 + a] = w4.x;
        Wqs[(c4 + 1) * 132 + a] = w4.y;
        Wqs[(c4 + 2) * 132 + a] = w4.z;
        Wqs[(c4 + 3) * 132 + a] = w4.w;
    }
    for (int i = tid; i < 8 * 32; i += 256) {
        int b  = i >> 5;
        int c4 = (i & 31) * 4;
        *reinterpret_cast<float4*>(&Wks[b * 132 + c4]) =
            *reinterpret_cast<const float4*>(&Wk_l[(b0 + b) * 128 + c4]);
    }
    if (tid < 128) bqs[tid] = bq_l[tid];
    __syncthreads();

    const int a  = tid & 127;
    const int bh = tid >> 7;
    float acc[4] = {0.f, 0.f, 0.f, 0.f};
    #pragma unroll 4
    for (int c = 0; c < 128; c++) {
        float wq = Wqs[c * 132 + a];
        #pragma unroll
        for (int j = 0; j < 4; j++)
            acc[j] += wq * Wks[(bh * 4 + j) * 132 + c];
    }
    #pragma unroll
    for (int j = 0; j < 4; j++)
        g_M[(size_t)layer * HD * HD + a * 128 + b0 + bh * 4 + j] = acc[j] * SCALE;

    if (tid < 8) {
        float s = 0.f;
        for (int c = 0; c < 128; c++) s += Wks[tid * 132 + c] * bqs[c];
        g_w[layer * HD + b0 + tid] = s * SCALE;
    }
}

// ==================== fused per-layer GEMM (3 outputs + beta) ====================
// y=0: qm (fp32 out) — HFMA2 path unless force32 (input projection)
// y=1: v  (fp16 out -> kv) — HFMA2 path
// y=2: s  (fp32 out) — always FFMA path (direct h path, precision-critical)
#define GPITCH 132
#define HPITCH_A 132
#define HPITCH_B 68
#define GEMM_SMEM (2 * 128 * GPITCH * 4)

__global__ __launch_bounds__(256, 1)
void gemm3(const float* __restrict__ A,
           const float* __restrict__ W0, const float* __restrict__ W1,
           const float* __restrict__ W2,
           const float* __restrict__ b0, const float* __restrict__ b1,
           const float* __restrict__ b2,
           float* __restrict__ out0, __half* __restrict__ kvv,
           float* __restrict__ out2, __half* __restrict__ kv_h_dual,
           const float* __restrict__ wvec, float* __restrict__ betap,
           int force32, int nrows)
{
    extern __shared__ float sm[];
    __shared__ float wsh[128];

    const int y = blockIdx.y;
    const float* W    = (y == 0) ? W0 : (y == 1) ? W1 : W2;
    const float* bias = (y == 0) ? b0 : (y == 1) ? b1 : b2;
    const bool half_path = (y < 2) && !force32;

    const int tid  = threadIdx.x;
    const int row0 = blockIdx.x * 128;
    const int tx = tid & 15, ty = tid >> 4;
    const int r0 = ty * 8, c0 = tx * 8;

    float accf[8][8];
    #pragma unroll
    for (int i = 0; i < 8; i++)
        #pragma unroll
        for (int j = 0; j < 8; j++) accf[i][j] = 0.f;

    if (tid < 128) wsh[tid] = wvec ? wvec[tid] : 0.f;

    if (half_path) {
        uint32_t* As2 = reinterpret_cast<uint32_t*>(sm);
        uint32_t* Ws2 = As2 + 128 * HPITCH_A;

        #pragma unroll
        for (int c = 0; c < 16; c++) {
            int idx = c * 256 + tid;
            int r   = idx & 127;
            int kq  = (idx >> 7) * 4;
            int ar  = row0 + r;
            float4 a4 = make_float4(0.f, 0.f, 0.f, 0.f);
            if (ar < nrows) a4 = *reinterpret_cast<const float4*>(&A[(size_t)ar * 128 + kq]);
            __half2 d0 = __half2half2(__float2half_rn(a4.x));
            __half2 d1 = __half2half2(__float2half_rn(a4.y));
            __half2 d2 = __half2half2(__float2half_rn(a4.z));
            __half2 d3 = __half2half2(__float2half_rn(a4.w));
            As2[(kq + 0) * HPITCH_A + r] = *reinterpret_cast<uint32_t*>(&d0);
            As2[(kq + 1) * HPITCH_A + r] = *reinterpret_cast<uint32_t*>(&d1);
            As2[(kq + 2) * HPITCH_A + r] = *reinterpret_cast<uint32_t*>(&d2);
            As2[(kq + 3) * HPITCH_A + r] = *reinterpret_cast<uint32_t*>(&d3);
        }
        #pragma unroll
        for (int c = 0; c < 16; c++) {
            int idx = c * 256 + tid;
            int r   = idx >> 5;
            int c4  = (idx & 31) * 4;
            float4 w4 = *reinterpret_cast<const float4*>(&W[r * 128 + c4]);
            __half2 p0 = __floats2half2_rn(w4.x, w4.y);
            __half2 p1 = __floats2half2_rn(w4.z, w4.w);
            uint2 pu;
            pu.x = *reinterpret_cast<uint32_t*>(&p0);
            pu.y = *reinterpret_cast<uint32_t*>(&p1);
            *reinterpret_cast<uint2*>(&Ws2[r * HPITCH_B + (c4 >> 1)]) = pu;
        }
        __syncthreads();

        const __half2 z2 = __float2half2_rn(0.f);
        #pragma unroll
        for (int kc = 0; kc < 8; kc++) {
            __half2 acc2[8][4];
            #pragma unroll
            for (int i = 0; i < 8; i++)
                #pragma unroll
                for (int j = 0; j < 4; j++) acc2[i][j] = z2;

            #pragma unroll
            for (int kk = 0; kk < 16; kk++) {
                int k = kc * 16 + kk;
                uint4 au0 = *reinterpret_cast<const uint4*>(&As2[k * HPITCH_A + r0]);
                uint4 au1 = *reinterpret_cast<const uint4*>(&As2[k * HPITCH_A + r0 + 4]);
                uint4 bu  = *reinterpret_cast<const uint4*>(&Ws2[k * HPITCH_B + tx * 4]);
                __half2 a2[8], b2[4];
                a2[0] = *reinterpret_cast<__half2*>(&au0.x);
                a2[1] = *reinterpret_cast<__half2*>(&au0.y);
                a2[2] = *reinterpret_cast<__half2*>(&au0.z);
                a2[3] = *reinterpret_cast<__half2*>(&au0.w);
                a2[4] = *reinterpret_cast<__half2*>(&au1.x);
                a2[5] = *reinterpret_cast<__half2*>(&au1.y);
                a2[6] = *reinterpret_cast<__half2*>(&au1.z);
                a2[7] = *reinterpret_cast<__half2*>(&au1.w);
                b2[0] = *reinterpret_cast<__half2*>(&bu.x);
                b2[1] = *reinterpret_cast<__half2*>(&bu.y);
                b2[2] = *reinterpret_cast<__half2*>(&bu.z);
                b2[3] = *reinterpret_cast<__half2*>(&bu.w);
                #pragma unroll
                for (int i = 0; i < 8; i++)
                    #pragma unroll
                    for (int j = 0; j < 4; j++)
                        acc2[i][j] = __hfma2(a2[i], b2[j], acc2[i][j]);
            }
            #pragma unroll
            for (int i = 0; i < 8; i++)
                #pragma unroll
                for (int j = 0; j < 4; j++) {
                    float2 f = __half22float2(acc2[i][j]);
                    accf[i][2 * j]     += f.x;
                    accf[i][2 * j + 1] += f.y;
                }
        }

        if (y == 0 && betap != nullptr && tid < 128) {
            int rr = row0 + tid;
            if (rr < nrows) {
                float bsum = 0.f;
                #pragma unroll 8
                for (int b = 0; b < 128; b++) {
                    uint32_t u = As2[b * HPITCH_A + tid];
                    __half2 hv = *reinterpret_cast<__half2*>(&u);
                    bsum += __low2float(hv) * wsh[b];
                }
                betap[rr] = bsum;
            }
        }
    } else {
        float* AsT = sm;
        float* Ws  = sm + 128 * GPITCH;

        #pragma unroll
        for (int c = 0; c < 16; c++) {
            int idx = c * 256 + tid;
            int r   = idx & 127;
            int kq  = (idx >> 7) * 4;
            int ar  = row0 + r;
            float4 a4 = make_float4(0.f, 0.f, 0.f, 0.f);
            if (ar < nrows) a4 = *reinterpret_cast<const float4*>(&A[(size_t)ar * 128 + kq]);
            AsT[(kq + 0) * GPITCH + r] = a4.x;
            AsT[(kq + 1) * GPITCH + r] = a4.y;
            AsT[(kq + 2) * GPITCH + r] = a4.z;
            AsT[(kq + 3) * GPITCH + r] = a4.w;
        }
        #pragma unroll
        for (int c = 0; c < 16; c++) {
            int idx = c * 256 + tid;
            int r   = idx >> 5;
            int c4  = (idx & 31) * 4;
            *reinterpret_cast<float4*>(&Ws[r * GPITCH + c4]) =
                *reinterpret_cast<const float4*>(&W[r * 128 + c4]);
        }
        __syncthreads();

        #pragma unroll 8
        for (int k = 0; k < 128; k++) {
            float4 a0 = *reinterpret_cast<const float4*>(&AsT[k * GPITCH + r0]);
            float4 a1 = *reinterpret_cast<const float4*>(&AsT[k * GPITCH + r0 + 4]);
            float a[8] = {a0.x, a0.y, a0.z, a0.w, a1.x, a1.y, a1.z, a1.w};
            float4 bb0 = *reinterpret_cast<const float4*>(&Ws[k * GPITCH + c0]);
            float4 bb1 = *reinterpret_cast<const float4*>(&Ws[k * GPITCH + c0 + 4]);
            float b[8] = {bb0.x, bb0.y, bb0.z, bb0.w, bb1.x, bb1.y, bb1.z, bb1.w};
            #pragma unroll
            for (int i = 0; i < 8; i++)
                #pragma unroll
                for (int j = 0; j < 8; j++) accf[i][j] += a[i] * b[j];
        }

        if (y == 0 && betap != nullptr && tid < 128) {
            int rr = row0 + tid;
            if (rr < nrows) {
                float bsum = 0.f;
                #pragma unroll 8
                for (int b = 0; b < 128; b++) bsum += AsT[b * GPITCH + tid] * wsh[b];
                betap[rr] = bsum;
            }
        }
    }

    float bb[8];
    #pragma unroll
    for (int j = 0; j < 8; j++) bb[j] = bias[c0 + j];

    #pragma unroll
    for (int i = 0; i < 8; i++) {
        int r = row0 + r0 + i;
        if (r >= nrows) continue;
        float o[8];
        #pragma unroll
        for (int j = 0; j < 8; j++) o[j] = accf[i][j] + bb[j];
        if (y == 1) {
            __half2 h4[4];
            #pragma unroll
            for (int j = 0; j < 4; j++)
                h4[j] = __floats2half2_rn(o[2 * j], o[2 * j + 1]);
            *reinterpret_cast<uint4*>(&kvv[(size_t)r * 256 + 128 + c0]) =
                *reinterpret_cast<uint4*>(h4);
        } else {
            float* outf = (y == 0) ? out0 : out2;
            float4 o0 = make_float4(o[0], o[1], o[2], o[3]);
            float4 o1 = make_float4(o[4], o[5], o[6], o[7]);
            *reinterpret_cast<float4*>(&outf[(size_t)r * 128 + c0])     = o0;
            *reinterpret_cast<float4*>(&outf[(size_t)r * 128 + c0 + 4]) = o1;
            if (y == 0 && kv_h_dual) {
                __half2 h4[4];
                #pragma unroll
                for (int j = 0; j < 4; j++)
                    h4[j] = __floats2half2_rn(o[2 * j], o[2 * j + 1]);
                *reinterpret_cast<uint4*>(&kv_h_dual[(size_t)r * 256 + c0]) =
                    *reinterpret_cast<uint4*>(h4);
            }
        }
    }
}

// ==================== CSR build (once per launch) ====================
__global__ void csr_zero(int* __restrict__ deg) {
    int n = blockIdx.x * blockDim.x + threadIdx.x;
    if (n < N_NODES) deg[n] = 0;
}

__global__ __launch_bounds__(256)
void csr_count(const int* __restrict__ ei, int* __restrict__ deg) {
    int e = blockIdx.x * blockDim.x + threadIdx.x;
    if (e >= E_EDGES) return;
    atomicAdd(&deg[ei[E_EDGES + e]], 1);
}

__global__ __launch_bounds__(SCAN_BLK)
void csr_scan1(const int* __restrict__ deg, int* __restrict__ rowstart,
               int* __restrict__ bsum)
{
    __shared__ int wsum[32];
    const int tid  = threadIdx.x;
    const int lane = tid & 31;
    const int wid  = tid >> 5;
    const int n    = blockIdx.x * SCAN_BLK + tid;

    int v = (n < N_NODES) ? deg[n] : 0;
    int x = v;
    #pragma unroll
    for (int o = 1; o < 32; o <<= 1) {
        int yv = __shfl_up_sync(0xFFFFFFFFu, x, o);
        if (lane >= o) x += yv;
    }
    if (lane == 31) wsum[wid] = x;
    __syncthreads();
    if (wid == 0) {
        int w = wsum[lane];
        #pragma unroll
        for (int o = 1; o < 32; o <<= 1) {
            int yv = __shfl_up_sync(0xFFFFFFFFu, w, o);
            if (lane >= o) w += yv;
        }
        wsum[lane] = w;
    }
    __syncthreads();
    int excl = x - v + (wid ? wsum[wid - 1] : 0);
    if (n < N_NODES) rowstart[n] = excl;
    if (tid == SCAN_BLK - 1) bsum[blockIdx.x] = excl + v;
}

__global__ __launch_bounds__(128)
void csr_scan2(int* __restrict__ bsum)
{
    __shared__ int sh[NSCANB];
    const int tid = threadIdx.x;
    if (tid < NSCANB) sh[tid] = bsum[tid];
    __syncthreads();
    if (tid == 0) {
        int run = 0;
        for (int i = 0; i < NSCANB; i++) { int t = sh[i]; sh[i] = run; run += t; }
    }
    __syncthreads();
    if (tid < NSCANB) bsum[tid] = sh[tid];
}

__global__ __launch_bounds__(SCAN_BLK)
void csr_scan3(int* __restrict__ rowstart, int* __restrict__ cursor,
               const int* __restrict__ bsum)
{
    const int n = blockIdx.x * SCAN_BLK + threadIdx.x;
    if (n < N_NODES) {
        int r = rowstart[n] + bsum[blockIdx.x];
        rowstart[n] = r;
        cursor[n]   = r;
    }
    if (n == 0) rowstart[N_NODES] = E_EDGES;
}

__global__ __launch_bounds__(256)
void csr_scatter(const int* __restrict__ ei, int* __restrict__ cursor,
                 int* __restrict__ esrc)
{
    int e = blockIdx.x * blockDim.x + threadIdx.x;
    if (e >= E_EDGES) return;
    int dst  = ei[E_EDGES + e];
    int slot = atomicAdd(&cursor[dst], 1);
    esrc[slot] = ei[e];
}

// ==================== fused per-node attention layer (2-way ILP) ====================
// logit_e = qm[dst].h16[src] + beta[src]. Two independent edge chains (segment
// halves) double MLP + SHFL-chain parallelism; sums merge at the end (no
// max-shift, so den/acc are plain sums).
__global__ __launch_bounds__(256)
void gat_node(const int* __restrict__ rowstart, const int* __restrict__ esrc,
              const float* __restrict__ qm, const __half* __restrict__ kv_in,
              const float* __restrict__ beta, const float* __restrict__ skip,
              float* __restrict__ hout, __half* __restrict__ kv_out,
              int write_h16)
{
    const int wid  = threadIdx.x >> 5;
    const int lane = threadIdx.x & 31;
    const int n    = blockIdx.x * 8 + wid;
    if (n >= N_NODES) return;

    const int beg = rowstart[n];
    const int end = rowstart[n + 1];
    const int len  = end - beg;
    const int lenA = (len + 1) >> 1;
    const int mid  = beg + lenA;

    float4 q4 = *reinterpret_cast<const float4*>(&qm[(size_t)n * 128 + lane * 4]);
    float4 accA = make_float4(0.f, 0.f, 0.f, 0.f);
    float4 accB = make_float4(0.f, 0.f, 0.f, 0.f);
    float  denA = 0.f, denB = 0.f;

    for (int t = 0; t < lenA; t++) {
        const int iA = beg + t;
        const int iB = mid + t;
        const bool hasB = (iB < end);

        int sA = __ldg(&esrc[iA]);
        int sB = hasB ? __ldg(&esrc[iB]) : sA;

        uint2 kA = __ldg(reinterpret_cast<const uint2*>(&kv_in[(size_t)sA * 256 + lane * 4]));
        uint2 kB = __ldg(reinterpret_cast<const uint2*>(&kv_in[(size_t)sB * 256 + lane * 4]));
        uint2 vA = __ldg(reinterpret_cast<const uint2*>(&kv_in[(size_t)sA * 256 + 128 + lane * 4]));
        uint2 vB = __ldg(reinterpret_cast<const uint2*>(&kv_in[(size_t)sB * 256 + 128 + lane * 4]));
        float bA = __ldg(&beta[sA]);
        float bB = __ldg(&beta[sB]);

        float2 ka0 = __half22float2(*reinterpret_cast<__half2*>(&kA.x));
        float2 ka1 = __half22float2(*reinterpret_cast<__half2*>(&kA.y));
        float2 kb0 = __half22float2(*reinterpret_cast<__half2*>(&kB.x));
        float2 kb1 = __half22float2(*reinterpret_cast<__half2*>(&kB.y));

        float pA = q4.x * ka0.x + q4.y * ka0.y + q4.z * ka1.x + q4.w * ka1.y;
        float pB = q4.x * kb0.x + q4.y * kb0.y + q4.z * kb1.x + q4.w * kb1.y;
        #pragma unroll
        for (int off = 16; off > 0; off >>= 1) {
            pA += __shfl_xor_sync(0xFFFFFFFFu, pA, off);
            pB += __shfl_xor_sync(0xFFFFFFFFu, pB, off);
        }
        float eA = __expf(pA + bA);
        float eB = hasB ? __expf(pB + bB) : 0.f;

        float2 va0 = __half22float2(*reinterpret_cast<__half2*>(&vA.x));
        float2 va1 = __half22float2(*reinterpret_cast<__half2*>(&vA.y));
        float2 vb0 = __half22float2(*reinterpret_cast<__half2*>(&vB.x));
        float2 vb1 = __half22float2(*reinterpret_cast<__half2*>(&vB.y));

        denA   += eA;
        accA.x += eA * va0.x; accA.y += eA * va0.y;
        accA.z += eA * va1.x; accA.w += eA * va1.y;
        denB   += eB;
        accB.x += eB * vb0.x; accB.y += eB * vb0.y;
        accB.z += eB * vb1.x; accB.w += eB * vb1.y;
    }

    float den = denA + denB;
    float4 acc = make_float4(accA.x + accB.x, accA.y + accB.y,
                             accA.z + accB.z, accA.w + accB.w);

    float4 s4 = *reinterpret_cast<const float4*>(&skip[(size_t)n * 128 + lane * 4]);
    float inv = (len > 0) ? (1.f / den) : 0.f;
    float4 r;
    r.x = acc.x * inv + s4.x;
    r.y = acc.y * inv + s4.y;
    r.z = acc.z * inv + s4.z;
    r.w = acc.w * inv + s4.w;
    if (write_h16) {
        r.x = r.x > 0.f ? r.x : expm1f(r.x);
        r.y = r.y > 0.f ? r.y : expm1f(r.y);
        r.z = r.z > 0.f ? r.z : expm1f(r.z);
        r.w = r.w > 0.f ? r.w : expm1f(r.w);
        __half2 h0 = __floats2half2_rn(r.x, r.y);
        __half2 h1 = __floats2half2_rn(r.z, r.w);
        uint2 hv;
        hv.x = *reinterpret_cast<uint32_t*>(&h0);
        hv.y = *reinterpret_cast<uint32_t*>(&h1);
        *reinterpret_cast<uint2*>(&kv_out[(size_t)n * 256 + lane * 4]) = hv;
    }
    *reinterpret_cast<float4*>(&hout[(size_t)n * 128 + lane * 4]) = r;
}

// ---------------- classifier: out = log_softmax(h @ fcW + fcb) ----------------
__global__ __launch_bounds__(256)
void classifier(const float* __restrict__ h, const float* __restrict__ fcW,
                const float* __restrict__ fcb, float* __restrict__ out)
{
    __shared__ float Wsh[128 * 64];
    __shared__ float hs[8][128];

    int tid = threadIdx.x;
    for (int i = tid; i < 128 * 64; i += 256) {
        int r = i >> 6, c = i & 63;
        Wsh[i] = (c < OD) ? fcW[r * OD + c] : 0.f;
    }
    __syncthreads();

    int wid  = tid >> 5;
    int lane = tid & 31;
    int n    = blockIdx.x * 8 + wid;
    if (n >= N_NODES) return;

    reinterpret_cast<float4*>(hs[wid])[lane] =
        reinterpret_cast<const float4*>(&h[(size_t)n * 128])[lane];
    __syncwarp();

    float acc0 = 0.f, acc1 = 0.f;
    #pragma unroll 8
    for (int k = 0; k < 128; k++) {
        float hv = hs[wid][k];
        acc0 += hv * Wsh[k * 64 + lane];
        acc1 += hv * Wsh[k * 64 + 32 + lane];
    }
    float val0 = acc0 + fcb[lane];
    float val1 = (lane < 8) ? (acc1 + fcb[32 + lane]) : -__int_as_float(0x7F800000);

    float vmax = fmaxf(val0, val1);
    #pragma unroll
    for (int off = 16; off > 0; off >>= 1)
        vmax = fmaxf(vmax, __shfl_xor_sync(0xFFFFFFFFu, vmax, off));

    float s = __expf(val0 - vmax) + ((lane < 8) ? __expf(val1 - vmax) : 0.f);
    #pragma unroll
    for (int off = 16; off > 0; off >>= 1)
        s += __shfl_xor_sync(0xFFFFFFFFu, s, off);

    float lse = vmax + logf(s);
    out[(size_t)n * OD + lane] = val0 - lse;
    if (lane < 8) out[(size_t)n * OD + 32 + lane] = val1 - lse;
}

// ---------------- host launch ----------------
extern "C" void kernel_launch(void* const* d_in, const int* in_sizes, int n_in,
                              void* d_out, int out_size)
{
    const float* x     = (const float*)d_in[0];
    const int*   ei    = (const int*)  d_in[1];
    const float* lin_W = (const float*)d_in[2];
    const float* lin_b = (const float*)d_in[3];
    const float* Wq    = (const float*)d_in[4];
    const float* bq    = (const float*)d_in[5];
    const float* Wk    = (const float*)d_in[6];
    const float* bk    = (const float*)d_in[7];   // cancels in softmax; unused
    const float* Wv    = (const float*)d_in[8];
    const float* bv    = (const float*)d_in[9];
    const float* Wsk   = (const float*)d_in[10];
    const float* bsk   = (const float*)d_in[11];
    const float* fcW   = (const float*)d_in[12];
    const float* fcb   = (const float*)d_in[13];
    float* out = (float*)d_out;
    (void)bk;

    float *h, *qm, *s, *beta, *Mp, *wp, *zerop;
    __half *kv0, *kv1;
    int *deg, *rowstart, *cursor, *esrc, *bsum;
    cudaGetSymbolAddress((void**)&h,        g_h);
    cudaGetSymbolAddress((void**)&qm,       g_q);
    cudaGetSymbolAddress((void**)&s,        g_s);
    cudaGetSymbolAddress((void**)&beta,     g_beta);
    cudaGetSymbolAddress((void**)&Mp,       g_M);
    cudaGetSymbolAddress((void**)&wp,       g_w);
    cudaGetSymbolAddress((void**)&zerop,    g_zero);
    cudaGetSymbolAddress((void**)&kv0,      g_kv0);
    cudaGetSymbolAddress((void**)&kv1,      g_kv1);
    cudaGetSymbolAddress((void**)&deg,      g_deg);
    cudaGetSymbolAddress((void**)&rowstart, g_rowstart);
    cudaGetSymbolAddress((void**)&cursor,   g_cursor);
    cudaGetSymbolAddress((void**)&esrc,     g_esrc);
    cudaGetSymbolAddress((void**)&bsum,     g_bsum);

    cudaFuncSetAttribute(gemm3,    cudaFuncAttributeMaxDynamicSharedMemorySize, GEMM_SMEM);
    cudaFuncSetAttribute(prep_all, cudaFuncAttributeMaxDynamicSharedMemorySize, PREP_SMEM);

    const int GB  = (N_NODES + 127) / 128;
    const int NB  = (N_NODES + 255) / 256;
    const int ETB = (E_EDGES + 255) / 256;
    const int WNB = (N_NODES + 7) / 8;

    // ---- weights-only prep for all layers (one launch) ----
    prep_all<<<64, 256, PREP_SMEM>>>(Wq, Wk, bq);

    // ---- CSR build (monotonic parallel scan; deterministic layout) ----
    csr_zero<<<NB, 256>>>(deg);
    csr_count<<<ETB, 256>>>(ei, deg);
    csr_scan1<<<NSCANB, SCAN_BLK>>>(deg, rowstart, bsum);
    csr_scan2<<<1, 128>>>(bsum);
    csr_scan3<<<NSCANB, SCAN_BLK>>>(rowstart, cursor, bsum);
    csr_scatter<<<ETB, 256>>>(ei, cursor, esrc);

    // ---- input projection: fp32 path (force32=1), h + dual fp16 into kv0 ----
    gemm3<<<dim3(GB, 1), 256, GEMM_SMEM>>>(
        x, lin_W, lin_W, lin_W, lin_b, lin_b, lin_b,
        h, kv0, h, kv0, nullptr, nullptr, 1, N_NODES);

    for (int l = 0; l < NLAYERS; l++) {
        const float* Wv_l = Wv  + (size_t)l * HD * HD;
        const float* Ws_l = Wsk + (size_t)l * HD * HD;
        const float* bv_l = bv  + (size_t)l * HD;
        const float* bs_l = bsk + (size_t)l * HD;

        __half* kv_cur  = (l & 1) ? kv1 : kv0;
        __half* kv_next = (l & 1) ? kv0 : kv1;

        // qm (HFMA2), v (HFMA2), s (FFMA) in one launch
        gemm3<<<dim3(GB, 3), 256, GEMM_SMEM>>>(
            h, Mp + (size_t)l * HD * HD, Wv_l, Ws_l, zerop, bv_l, bs_l,
            qm, kv_cur, s, nullptr, wp + (size_t)l * HD, beta, 0, N_NODES);

        gat_node<<<WNB, 256>>>(rowstart, esrc, qm, kv_cur, beta, s, h, kv_next,
                               (l < NLAYERS - 1) ? 1 : 0);
    }

    classifier<<<WNB, 256>>>(h, fcW, fcb, out);
}